// round 1
// baseline (speedup 1.0000x reference)
#include <cuda_runtime.h>
#include <math.h>

// Problem constants
#define B_ 2
#define T_ 2048
#define C_ 768
#define H_ 12
#define HD_ 64
#define BT_ (B_ * T_)   // 4096

// ---------------------------------------------------------------------------
// Scratch (device globals; no allocation allowed)
// ---------------------------------------------------------------------------
__device__ float g_ln[BT_ * C_];          // LN output (reused for ln1 and ln2)
__device__ float g_qkv[BT_ * 3 * C_];     // QKV
__device__ float g_y[BT_ * C_];           // attention output (pre-proj)
__device__ float g_x1[BT_ * C_];          // x + attn
__device__ float g_h[BT_ * 4 * C_];       // gelu(fc)

// ---------------------------------------------------------------------------
// LayerNorm: one block (256 thr) per row of 768
// ---------------------------------------------------------------------------
__global__ void ln_kernel(const float* __restrict__ x, const float* __restrict__ g,
                          const float* __restrict__ b, float* __restrict__ out) {
    int row = blockIdx.x;
    const float* xr = x + (size_t)row * C_;
    float v[3];
    float s = 0.f, sq = 0.f;
#pragma unroll
    for (int i = 0; i < 3; i++) {
        v[i] = xr[threadIdx.x + i * 256];
        s += v[i];
        sq += v[i] * v[i];
    }
#pragma unroll
    for (int off = 16; off; off >>= 1) {
        s  += __shfl_xor_sync(0xffffffffu, s, off);
        sq += __shfl_xor_sync(0xffffffffu, sq, off);
    }
    __shared__ float ss[8], ssq[8];
    int w = threadIdx.x >> 5, lane = threadIdx.x & 31;
    if (lane == 0) { ss[w] = s; ssq[w] = sq; }
    __syncthreads();
    if (w == 0) {
        s = ss[lane & 7];
        sq = ssq[lane & 7];
#pragma unroll
        for (int off = 4; off; off >>= 1) {
            s  += __shfl_xor_sync(0xffffffffu, s, off);
            sq += __shfl_xor_sync(0xffffffffu, sq, off);
        }
        if (lane == 0) { ss[0] = s; ssq[0] = sq; }
    }
    __syncthreads();
    float mean = ss[0] * (1.0f / C_);
    float var  = ssq[0] * (1.0f / C_) - mean * mean;
    float rstd = rsqrtf(var + 1e-5f);
    float* outr = out + (size_t)row * C_;
#pragma unroll
    for (int i = 0; i < 3; i++) {
        int c = threadIdx.x + i * 256;
        outr[c] = (v[i] - mean) * rstd * g[c] + b[c];
    }
}

// ---------------------------------------------------------------------------
// SGEMM: C[M,N] = A[M,K] @ B[K,N], row-major. BM=BN=128, BK=8, 256 thr, 8x8.
// EPI: 0 = none, 1 = += res, 2 = exact GELU
// ---------------------------------------------------------------------------
template <int EPI>
__global__ __launch_bounds__(256, 2) void sgemm_kernel(
    const float* __restrict__ A, const float* __restrict__ Bm,
    const float* __restrict__ res, float* __restrict__ Cm,
    int M, int N, int K) {
    __shared__ float As[8][128];
    __shared__ float Bs[8][128];
    int tid = threadIdx.x;
    const float* Ab = A + (size_t)(blockIdx.y * 128) * K;
    const float* Bb = Bm + blockIdx.x * 128;
    int a_r = tid >> 1, a_c = (tid & 1) * 4;
    int b_r = tid >> 5, b_c = (tid & 31) * 4;
    int tr = (tid >> 4) * 8, tc = (tid & 15) * 8;
    float acc[8][8];
#pragma unroll
    for (int i = 0; i < 8; i++)
#pragma unroll
        for (int j = 0; j < 8; j++) acc[i][j] = 0.f;

    for (int k0 = 0; k0 < K; k0 += 8) {
        float4 av = *(const float4*)(Ab + (size_t)a_r * K + k0 + a_c);
        float4 bv = *(const float4*)(Bb + (size_t)(k0 + b_r) * N + b_c);
        As[a_c + 0][a_r] = av.x;
        As[a_c + 1][a_r] = av.y;
        As[a_c + 2][a_r] = av.z;
        As[a_c + 3][a_r] = av.w;
        *(float4*)&Bs[b_r][b_c] = bv;
        __syncthreads();
#pragma unroll
        for (int k = 0; k < 8; k++) {
            float4 a0 = *(const float4*)&As[k][tr];
            float4 a1 = *(const float4*)&As[k][tr + 4];
            float4 b0 = *(const float4*)&Bs[k][tc];
            float4 b1 = *(const float4*)&Bs[k][tc + 4];
            float ar[8] = {a0.x, a0.y, a0.z, a0.w, a1.x, a1.y, a1.z, a1.w};
            float br[8] = {b0.x, b0.y, b0.z, b0.w, b1.x, b1.y, b1.z, b1.w};
#pragma unroll
            for (int i = 0; i < 8; i++)
#pragma unroll
                for (int j = 0; j < 8; j++) acc[i][j] += ar[i] * br[j];
        }
        __syncthreads();
    }

    int row0 = blockIdx.y * 128 + tr;
    int col0 = blockIdx.x * 128 + tc;
#pragma unroll
    for (int i = 0; i < 8; i++) {
        size_t off = (size_t)(row0 + i) * N + col0;
#pragma unroll
        for (int j = 0; j < 8; j++) {
            float vv = acc[i][j];
            if (EPI == 1) vv += res[off + j];
            if (EPI == 2) vv = 0.5f * vv * (1.0f + erff(vv * 0.7071067811865475f));
            Cm[off + j] = vv;
        }
    }
}

// ---------------------------------------------------------------------------
// Flash attention (fp32, causal). Grid: (T/64, B*H). 256 threads.
// Block handles 64 queries; iterates 32-key tiles with online softmax.
// ---------------------------------------------------------------------------
__global__ __launch_bounds__(256) void attn_kernel(const float* __restrict__ qkv,
                                                   float* __restrict__ y) {
    __shared__ float Qs[64][64];
    __shared__ float Kt[64][33];   // transposed K tile, padded
    __shared__ float Vs[32][64];
    __shared__ float Ps[64][32];

    int qb = blockIdx.x, bh = blockIdx.y;
    int b = bh / H_, h = bh % H_;
    const float* base = qkv + (size_t)b * T_ * 3 * C_ + h * HD_;
    int tid = threadIdx.x;

    // Load Q tile (64x64)
#pragma unroll
    for (int i = 0; i < 16; i++) {
        int idx = tid + i * 256;
        int r = idx >> 6, d = idx & 63;
        Qs[r][d] = base[(size_t)(qb * 64 + r) * 3 * C_ + d];
    }

    int ty = tid >> 4, tx = tid & 15;
    int r0 = ty * 4, c0 = tx * 2, d0 = tx * 4;

    float m[4], l[4], acc[4][4];
#pragma unroll
    for (int i = 0; i < 4; i++) {
        m[i] = -1e30f;
        l[i] = 0.f;
#pragma unroll
        for (int j = 0; j < 4; j++) acc[i][j] = 0.f;
    }

    int jend = 2 * qb + 2;
    for (int j = 0; j < jend; j++) {
        __syncthreads();
        // Load K (transposed) and V tiles (32 x 64)
#pragma unroll
        for (int i = 0; i < 8; i++) {
            int idx = tid + i * 256;
            int c = idx >> 6, d = idx & 63;
            size_t roff = (size_t)(j * 32 + c) * 3 * C_ + d;
            Kt[d][c] = base[roff + C_];
            Vs[c][d] = base[roff + 2 * C_];
        }
        __syncthreads();

        // S = Q K^T  (each thread: 4 rows x 2 cols)
        float s[4][2] = {{0.f, 0.f}, {0.f, 0.f}, {0.f, 0.f}, {0.f, 0.f}};
#pragma unroll
        for (int k = 0; k < 64; k++) {
            float k0v = Kt[k][c0], k1v = Kt[k][c0 + 1];
#pragma unroll
            for (int i = 0; i < 4; i++) {
                float qv = Qs[r0 + i][k];
                s[i][0] += qv * k0v;
                s[i][1] += qv * k1v;
            }
        }

        bool need_mask = (j >= 2 * qb);
#pragma unroll
        for (int i = 0; i < 4; i++) {
            int q = qb * 64 + r0 + i;
#pragma unroll
            for (int jj = 0; jj < 2; jj++) {
                s[i][jj] *= 0.125f;  // 1/sqrt(64)
                if (need_mask && (j * 32 + c0 + jj) > q) s[i][jj] = -1e30f;
            }
        }

        // Online softmax, rows reduced across 16-lane groups
#pragma unroll
        for (int i = 0; i < 4; i++) {
            float mloc = fmaxf(s[i][0], s[i][1]);
#pragma unroll
            for (int off = 1; off < 16; off <<= 1)
                mloc = fmaxf(mloc, __shfl_xor_sync(0xffffffffu, mloc, off));
            float mn = fmaxf(m[i], mloc);
            float corr = __expf(m[i] - mn);
            float p0 = __expf(s[i][0] - mn);
            float p1 = __expf(s[i][1] - mn);
            float ps = p0 + p1;
#pragma unroll
            for (int off = 1; off < 16; off <<= 1)
                ps += __shfl_xor_sync(0xffffffffu, ps, off);
            l[i] = l[i] * corr + ps;
            m[i] = mn;
#pragma unroll
            for (int d = 0; d < 4; d++) acc[i][d] *= corr;
            Ps[r0 + i][c0] = p0;
            Ps[r0 + i][c0 + 1] = p1;
        }
        __syncthreads();

        // O += P V  (each thread: 4 rows x 4 head-dims)
#pragma unroll
        for (int c = 0; c < 32; c++) {
            float4 v4 = *(const float4*)&Vs[c][d0];
#pragma unroll
            for (int i = 0; i < 4; i++) {
                float pv = Ps[r0 + i][c];
                acc[i][0] += pv * v4.x;
                acc[i][1] += pv * v4.y;
                acc[i][2] += pv * v4.z;
                acc[i][3] += pv * v4.w;
            }
        }
    }

    // Write normalized output
#pragma unroll
    for (int i = 0; i < 4; i++) {
        float inv = 1.0f / l[i];
        int q = qb * 64 + r0 + i;
        size_t o = (size_t)(b * T_ + q) * C_ + h * HD_ + d0;
        y[o + 0] = acc[i][0] * inv;
        y[o + 1] = acc[i][1] * inv;
        y[o + 2] = acc[i][2] * inv;
        y[o + 3] = acc[i][3] * inv;
    }
}

// ---------------------------------------------------------------------------
// Launch
// ---------------------------------------------------------------------------
extern "C" void kernel_launch(void* const* d_in, const int* in_sizes, int n_in,
                              void* d_out, int out_size) {
    const float* x       = (const float*)d_in[0];
    const float* ln1_g   = (const float*)d_in[1];
    const float* ln1_b   = (const float*)d_in[2];
    const float* W_qkv   = (const float*)d_in[3];
    const float* W_attn  = (const float*)d_in[4];
    const float* ln2_g   = (const float*)d_in[5];
    const float* ln2_b   = (const float*)d_in[6];
    const float* W_fc    = (const float*)d_in[7];
    const float* W_mlp   = (const float*)d_in[8];
    float* out = (float*)d_out;

    float *ln, *qkv, *yb, *x1, *hb;
    cudaGetSymbolAddress((void**)&ln, g_ln);
    cudaGetSymbolAddress((void**)&qkv, g_qkv);
    cudaGetSymbolAddress((void**)&yb, g_y);
    cudaGetSymbolAddress((void**)&x1, g_x1);
    cudaGetSymbolAddress((void**)&hb, g_h);

    // 1) LN1
    ln_kernel<<<BT_, 256>>>(x, ln1_g, ln1_b, ln);
    // 2) QKV = ln1 @ W_qkv  [4096 x 2304 x 768]
    sgemm_kernel<0><<<dim3(2304 / 128, BT_ / 128), 256>>>(ln, W_qkv, nullptr, qkv,
                                                          BT_, 3 * C_, C_);
    // 3) causal flash attention
    attn_kernel<<<dim3(T_ / 64, B_ * H_), 256>>>(qkv, yb);
    // 4) x1 = x + y @ W_attn_proj  [4096 x 768 x 768]
    sgemm_kernel<1><<<dim3(C_ / 128, BT_ / 128), 256>>>(yb, W_attn, x, x1,
                                                        BT_, C_, C_);
    // 5) LN2
    ln_kernel<<<BT_, 256>>>(x1, ln2_g, ln2_b, ln);
    // 6) h = gelu(ln2 @ W_fc)  [4096 x 3072 x 768]
    sgemm_kernel<2><<<dim3(3072 / 128, BT_ / 128), 256>>>(ln, W_fc, nullptr, hb,
                                                          BT_, 4 * C_, C_);
    // 7) out = x1 + h @ W_mlp_proj  [4096 x 768 x 3072]
    sgemm_kernel<1><<<dim3(C_ / 128, BT_ / 128), 256>>>(hb, W_mlp, x1, out,
                                                        BT_, C_, 4 * C_);
}

// round 3
// speedup vs baseline: 2.3049x; 2.3049x over previous
#include <cuda_runtime.h>
#include <math.h>
#include <stdint.h>

// Problem constants
#define B_ 2
#define T_ 2048
#define C_ 768
#define H_ 12
#define HD_ 64
#define BT_ (B_ * T_)   // 4096

// ---------------------------------------------------------------------------
// Scratch (device globals; no allocation allowed)
// ---------------------------------------------------------------------------
__device__ float g_ln[BT_ * C_];          // LN output (tf32-rounded)
__device__ float g_qkv[BT_ * 3 * C_];     // QKV (fp32)
__device__ float g_y[BT_ * C_];           // attention output (tf32-rounded)
__device__ float g_x1[BT_ * C_];          // x + attn (fp32)
__device__ float g_h[BT_ * 4 * C_];       // gelu(fc) (tf32-rounded)
// Transposed weights [N,K] row-major (tf32-rounded)
__device__ float g_wt_qkv[3 * C_ * C_];
__device__ float g_wt_attn[C_ * C_];
__device__ float g_wt_fc[4 * C_ * C_];
__device__ float g_wt_mlp[C_ * 4 * C_];

// ---------------------------------------------------------------------------
// Helpers
// ---------------------------------------------------------------------------
__device__ __forceinline__ float to_tf32(float x) {
    uint32_t u;
    asm("cvt.rna.tf32.f32 %0, %1;" : "=r"(u) : "f"(x));
    return __uint_as_float(u);
}

__device__ __forceinline__ uint32_t smem_u32(const void* p) {
    uint32_t a;
    asm("{ .reg .u64 t; cvta.to.shared.u64 t, %1; cvt.u32.u64 %0, t; }"
        : "=r"(a) : "l"(p));
    return a;
}

#define CP_ASYNC16(dst, src) \
    asm volatile("cp.async.cg.shared.global [%0], [%1], 16;" :: "r"(dst), "l"(src))
#define CP_COMMIT() asm volatile("cp.async.commit_group;" ::: "memory")
#define CP_WAIT(n)  asm volatile("cp.async.wait_group %0;" :: "n"(n) : "memory")

__device__ __forceinline__ void mma_tf32(float* d, const float* a, const float* b) {
    asm volatile(
        "mma.sync.aligned.m16n8k8.row.col.f32.tf32.tf32.f32 "
        "{%0,%1,%2,%3}, {%4,%5,%6,%7}, {%8,%9}, {%0,%1,%2,%3};"
        : "+f"(d[0]), "+f"(d[1]), "+f"(d[2]), "+f"(d[3])
        : "r"(__float_as_uint(a[0])), "r"(__float_as_uint(a[1])),
          "r"(__float_as_uint(a[2])), "r"(__float_as_uint(a[3])),
          "r"(__float_as_uint(b[0])), "r"(__float_as_uint(b[1])));
}

// swizzled smem index for [row][32-k] tiles: kills all LDS bank conflicts for
// the mma fragment access pattern (8 consecutive rows x 4 consecutive k)
#define SWIDX(m, k) ((m) * 32 + ((k) ^ (((m) & 7) << 2)))

// ---------------------------------------------------------------------------
// Weight transpose: out[N,K] = tf32(in[K,N]).  grid(N/32, K/32), block(32,8)
// ---------------------------------------------------------------------------
__global__ void transpose_kernel(const float* __restrict__ in, float* __restrict__ out,
                                 int K, int N) {
    __shared__ float tile[32][33];
    int n0 = blockIdx.x * 32, k0 = blockIdx.y * 32;
    int n = n0 + threadIdx.x;
#pragma unroll
    for (int i = threadIdx.y; i < 32; i += 8)
        tile[i][threadIdx.x] = in[(size_t)(k0 + i) * N + n];
    __syncthreads();
    int k = k0 + threadIdx.x;
#pragma unroll
    for (int i = threadIdx.y; i < 32; i += 8)
        out[(size_t)(n0 + i) * K + k] = to_tf32(tile[threadIdx.x][i]);
}

// ---------------------------------------------------------------------------
// LayerNorm: one block (256 thr) per row of 768.  Output tf32-rounded.
// ---------------------------------------------------------------------------
__global__ void ln_kernel(const float* __restrict__ x, const float* __restrict__ g,
                          const float* __restrict__ b, float* __restrict__ out) {
    int row = blockIdx.x;
    const float* xr = x + (size_t)row * C_;
    float v[3];
    float s = 0.f, sq = 0.f;
#pragma unroll
    for (int i = 0; i < 3; i++) {
        v[i] = xr[threadIdx.x + i * 256];
        s += v[i];
        sq += v[i] * v[i];
    }
#pragma unroll
    for (int off = 16; off; off >>= 1) {
        s  += __shfl_xor_sync(0xffffffffu, s, off);
        sq += __shfl_xor_sync(0xffffffffu, sq, off);
    }
    __shared__ float ss[8], ssq[8];
    int w = threadIdx.x >> 5, lane = threadIdx.x & 31;
    if (lane == 0) { ss[w] = s; ssq[w] = sq; }
    __syncthreads();
    if (w == 0) {
        s = ss[lane & 7];
        sq = ssq[lane & 7];
#pragma unroll
        for (int off = 4; off; off >>= 1) {
            s  += __shfl_xor_sync(0xffffffffu, s, off);
            sq += __shfl_xor_sync(0xffffffffu, sq, off);
        }
        if (lane == 0) { ss[0] = s; ssq[0] = sq; }
    }
    __syncthreads();
    float mean = ss[0] * (1.0f / C_);
    float var  = ssq[0] * (1.0f / C_) - mean * mean;
    float rstd = rsqrtf(var + 1e-5f);
    float* outr = out + (size_t)row * C_;
#pragma unroll
    for (int i = 0; i < 3; i++) {
        int c = threadIdx.x + i * 256;
        outr[c] = to_tf32((v[i] - mean) * rstd * g[c] + b[c]);
    }
}

// ---------------------------------------------------------------------------
// mma.sync tf32 GEMM: C[M,N] = A[M,K] @ Bt[N,K]^T (both row-major, K-major).
// BM=BN=128, BK=32, double-buffered cp.async, 256 threads (8 warps, 64x32 each)
// EPI: 0 = none, 1 = += res, 2 = exact GELU (+ tf32 round)
// ---------------------------------------------------------------------------
#define STAGE_FLOATS 4096   // 128*32
#define GEMM_SMEM (2 * 2 * STAGE_FLOATS * 4)   // 2 stages x (A+B) = 64KB

__device__ __forceinline__ void load_stage(uint32_t sa, uint32_t sb,
                                           const float* __restrict__ Ab,
                                           const float* __restrict__ Bb,
                                           int K, int kb, int tid) {
    int k0 = kb * 32;
#pragma unroll
    for (int t = 0; t < 4; t++) {
        int linear = tid + t * 256;        // 0..1023
        int m = linear >> 3, ch = linear & 7;
        uint32_t sw = (uint32_t)((m * 32 + ((ch * 4) ^ ((m & 7) << 2))) * 4);
        const float* asrc = Ab + (size_t)m * K + k0 + ch * 4;
        const float* bsrc = Bb + (size_t)m * K + k0 + ch * 4;
        CP_ASYNC16(sa + sw, asrc);
        CP_ASYNC16(sb + sw, bsrc);
    }
}

template <int EPI>
__global__ __launch_bounds__(256)
void tc_gemm(const float* __restrict__ A, const float* __restrict__ Bt,
             const float* __restrict__ res, float* __restrict__ Cm,
             int M, int N, int K) {
    extern __shared__ __align__(16) float dsm[];
    float* smA = dsm;                        // [2][4096]
    float* smB = dsm + 2 * STAGE_FLOATS;     // [2][4096]
    uint32_t saA = smem_u32(smA);
    uint32_t saB = smem_u32(smB);

    int tid = threadIdx.x;
    int wid = tid >> 5, lane = tid & 31;
    int warp_m = wid >> 2, warp_n = wid & 3;   // 2 x 4 warp grid
    int lr = lane >> 2, lc = lane & 3;
    const int KB = K >> 5;

    const float* Ab = A + (size_t)blockIdx.y * 128 * K;
    const float* Bb = Bt + (size_t)blockIdx.x * 128 * K;

    float acc[4][4][4];
#pragma unroll
    for (int i = 0; i < 4; i++)
#pragma unroll
        for (int j = 0; j < 4; j++)
#pragma unroll
            for (int r = 0; r < 4; r++) acc[i][j][r] = 0.f;

    load_stage(saA, saB, Ab, Bb, K, 0, tid);
    CP_COMMIT();

    for (int kb = 0; kb < KB; kb++) {
        int s = kb & 1;
        if (kb + 1 < KB) {
            load_stage(saA + (s ^ 1) * STAGE_FLOATS * 4,
                       saB + (s ^ 1) * STAGE_FLOATS * 4, Ab, Bb, K, kb + 1, tid);
            CP_COMMIT();
            CP_WAIT(1);
        } else {
            CP_WAIT(0);
        }
        __syncthreads();

        const float* as = smA + s * STAGE_FLOATS;
        const float* bs = smB + s * STAGE_FLOATS;
#pragma unroll
        for (int ks = 0; ks < 4; ks++) {
            int k0 = ks * 8;
            float afr[4][4], bfr[4][2];
#pragma unroll
            for (int mt = 0; mt < 4; mt++) {
                int r0 = warp_m * 64 + mt * 16 + lr;
                afr[mt][0] = as[SWIDX(r0,     k0 + lc)];
                afr[mt][1] = as[SWIDX(r0 + 8, k0 + lc)];
                afr[mt][2] = as[SWIDX(r0,     k0 + lc + 4)];
                afr[mt][3] = as[SWIDX(r0 + 8, k0 + lc + 4)];
            }
#pragma unroll
            for (int nt = 0; nt < 4; nt++) {
                int n0 = warp_n * 32 + nt * 8 + lr;
                bfr[nt][0] = bs[SWIDX(n0, k0 + lc)];
                bfr[nt][1] = bs[SWIDX(n0, k0 + lc + 4)];
            }
#pragma unroll
            for (int mt = 0; mt < 4; mt++)
#pragma unroll
                for (int nt = 0; nt < 4; nt++)
                    mma_tf32(acc[mt][nt], afr[mt], bfr[nt]);
        }
        __syncthreads();
    }

    // Epilogue: direct float2 stores
    int gm0 = blockIdx.y * 128 + warp_m * 64;
    int gn0 = blockIdx.x * 128 + warp_n * 32;
#pragma unroll
    for (int mt = 0; mt < 4; mt++) {
#pragma unroll
        for (int nt = 0; nt < 4; nt++) {
            int gm = gm0 + mt * 16 + lr;
            int gn = gn0 + nt * 8 + lc * 2;
#pragma unroll
            for (int half = 0; half < 2; half++) {
                int row = gm + half * 8;
                size_t off = (size_t)row * N + gn;
                float2 v;
                v.x = acc[mt][nt][half * 2 + 0];
                v.y = acc[mt][nt][half * 2 + 1];
                if (EPI == 1) {
                    float2 rs = *(const float2*)(res + off);
                    v.x += rs.x; v.y += rs.y;
                }
                if (EPI == 2) {
                    v.x = to_tf32(0.5f * v.x * (1.0f + erff(v.x * 0.7071067811865475f)));
                    v.y = to_tf32(0.5f * v.y * (1.0f + erff(v.y * 0.7071067811865475f)));
                }
                *(float2*)(Cm + off) = v;
            }
        }
    }
}

// ---------------------------------------------------------------------------
// Flash attention (fp32, causal). Grid: (T/64, B*H). 256 threads.
// ---------------------------------------------------------------------------
__global__ __launch_bounds__(256) void attn_kernel(const float* __restrict__ qkv,
                                                   float* __restrict__ y) {
    __shared__ float Qs[64][64];
    __shared__ float Kt[64][33];
    __shared__ float Vs[32][64];
    __shared__ float Ps[64][32];

    int qb = blockIdx.x, bh = blockIdx.y;
    int b = bh / H_, h = bh % H_;
    const float* base = qkv + (size_t)b * T_ * 3 * C_ + h * HD_;
    int tid = threadIdx.x;

#pragma unroll
    for (int i = 0; i < 16; i++) {
        int idx = tid + i * 256;
        int r = idx >> 6, d = idx & 63;
        Qs[r][d] = base[(size_t)(qb * 64 + r) * 3 * C_ + d];
    }

    int ty = tid >> 4, tx = tid & 15;
    int r0 = ty * 4, c0 = tx * 2, d0 = tx * 4;

    float m[4], l[4], acc[4][4];
#pragma unroll
    for (int i = 0; i < 4; i++) {
        m[i] = -1e30f;
        l[i] = 0.f;
#pragma unroll
        for (int j = 0; j < 4; j++) acc[i][j] = 0.f;
    }

    int jend = 2 * qb + 2;
    for (int j = 0; j < jend; j++) {
        __syncthreads();
#pragma unroll
        for (int i = 0; i < 8; i++) {
            int idx = tid + i * 256;
            int c = idx >> 6, d = idx & 63;
            size_t roff = (size_t)(j * 32 + c) * 3 * C_ + d;
            Kt[d][c] = base[roff + C_];
            Vs[c][d] = base[roff + 2 * C_];
        }
        __syncthreads();

        float s[4][2] = {{0.f, 0.f}, {0.f, 0.f}, {0.f, 0.f}, {0.f, 0.f}};
#pragma unroll
        for (int k = 0; k < 64; k++) {
            float k0v = Kt[k][c0], k1v = Kt[k][c0 + 1];
#pragma unroll
            for (int i = 0; i < 4; i++) {
                float qv = Qs[r0 + i][k];
                s[i][0] += qv * k0v;
                s[i][1] += qv * k1v;
            }
        }

        bool need_mask = (j >= 2 * qb);
#pragma unroll
        for (int i = 0; i < 4; i++) {
            int q = qb * 64 + r0 + i;
#pragma unroll
            for (int jj = 0; jj < 2; jj++) {
                s[i][jj] *= 0.125f;
                if (need_mask && (j * 32 + c0 + jj) > q) s[i][jj] = -1e30f;
            }
        }

#pragma unroll
        for (int i = 0; i < 4; i++) {
            float mloc = fmaxf(s[i][0], s[i][1]);
#pragma unroll
            for (int off = 1; off < 16; off <<= 1)
                mloc = fmaxf(mloc, __shfl_xor_sync(0xffffffffu, mloc, off));
            float mn = fmaxf(m[i], mloc);
            float corr = __expf(m[i] - mn);
            float p0 = __expf(s[i][0] - mn);
            float p1 = __expf(s[i][1] - mn);
            float ps = p0 + p1;
#pragma unroll
            for (int off = 1; off < 16; off <<= 1)
                ps += __shfl_xor_sync(0xffffffffu, ps, off);
            l[i] = l[i] * corr + ps;
            m[i] = mn;
#pragma unroll
            for (int d = 0; d < 4; d++) acc[i][d] *= corr;
            Ps[r0 + i][c0] = p0;
            Ps[r0 + i][c0 + 1] = p1;
        }
        __syncthreads();

#pragma unroll
        for (int c = 0; c < 32; c++) {
            float4 v4 = *(const float4*)&Vs[c][d0];
#pragma unroll
            for (int i = 0; i < 4; i++) {
                float pv = Ps[r0 + i][c];
                acc[i][0] += pv * v4.x;
                acc[i][1] += pv * v4.y;
                acc[i][2] += pv * v4.z;
                acc[i][3] += pv * v4.w;
            }
        }
    }

#pragma unroll
    for (int i = 0; i < 4; i++) {
        float inv = 1.0f / l[i];
        int q = qb * 64 + r0 + i;
        size_t o = (size_t)(b * T_ + q) * C_ + h * HD_ + d0;
        y[o + 0] = to_tf32(acc[i][0] * inv);
        y[o + 1] = to_tf32(acc[i][1] * inv);
        y[o + 2] = to_tf32(acc[i][2] * inv);
        y[o + 3] = to_tf32(acc[i][3] * inv);
    }
}

// ---------------------------------------------------------------------------
// Launch
// ---------------------------------------------------------------------------
extern "C" void kernel_launch(void* const* d_in, const int* in_sizes, int n_in,
                              void* d_out, int out_size) {
    const float* x       = (const float*)d_in[0];
    const float* ln1_g   = (const float*)d_in[1];
    const float* ln1_b   = (const float*)d_in[2];
    const float* W_qkv   = (const float*)d_in[3];
    const float* W_attn  = (const float*)d_in[4];
    const float* ln2_g   = (const float*)d_in[5];
    const float* ln2_b   = (const float*)d_in[6];
    const float* W_fc    = (const float*)d_in[7];
    const float* W_mlp   = (const float*)d_in[8];
    float* out = (float*)d_out;

    float *ln, *qkv, *yb, *x1, *hb;
    float *wtq, *wta, *wtf, *wtm;
    cudaGetSymbolAddress((void**)&ln, g_ln);
    cudaGetSymbolAddress((void**)&qkv, g_qkv);
    cudaGetSymbolAddress((void**)&yb, g_y);
    cudaGetSymbolAddress((void**)&x1, g_x1);
    cudaGetSymbolAddress((void**)&hb, g_h);
    cudaGetSymbolAddress((void**)&wtq, g_wt_qkv);
    cudaGetSymbolAddress((void**)&wta, g_wt_attn);
    cudaGetSymbolAddress((void**)&wtf, g_wt_fc);
    cudaGetSymbolAddress((void**)&wtm, g_wt_mlp);

    cudaFuncSetAttribute(tc_gemm<0>, cudaFuncAttributeMaxDynamicSharedMemorySize, GEMM_SMEM);
    cudaFuncSetAttribute(tc_gemm<1>, cudaFuncAttributeMaxDynamicSharedMemorySize, GEMM_SMEM);
    cudaFuncSetAttribute(tc_gemm<2>, cudaFuncAttributeMaxDynamicSharedMemorySize, GEMM_SMEM);

    // 0) transpose weights to [N,K] (tf32-rounded)
    transpose_kernel<<<dim3(3 * C_ / 32, C_ / 32), dim3(32, 8)>>>(W_qkv, wtq, C_, 3 * C_);
    transpose_kernel<<<dim3(C_ / 32, C_ / 32), dim3(32, 8)>>>(W_attn, wta, C_, C_);
    transpose_kernel<<<dim3(4 * C_ / 32, C_ / 32), dim3(32, 8)>>>(W_fc, wtf, C_, 4 * C_);
    transpose_kernel<<<dim3(C_ / 32, 4 * C_ / 32), dim3(32, 8)>>>(W_mlp, wtm, 4 * C_, C_);

    // 1) LN1
    ln_kernel<<<BT_, 256>>>(x, ln1_g, ln1_b, ln);
    // 2) QKV = ln1 @ W_qkv
    tc_gemm<0><<<dim3(3 * C_ / 128, BT_ / 128), 256, GEMM_SMEM>>>(ln, wtq, nullptr, qkv,
                                                                  BT_, 3 * C_, C_);
    // 3) causal flash attention
    attn_kernel<<<dim3(T_ / 64, B_ * H_), 256>>>(qkv, yb);
    // 4) x1 = x + y @ W_attn_proj
    tc_gemm<1><<<dim3(C_ / 128, BT_ / 128), 256, GEMM_SMEM>>>(yb, wta, x, x1,
                                                              BT_, C_, C_);
    // 5) LN2
    ln_kernel<<<BT_, 256>>>(x1, ln2_g, ln2_b, ln);
    // 6) h = gelu(ln2 @ W_fc)
    tc_gemm<2><<<dim3(4 * C_ / 128, BT_ / 128), 256, GEMM_SMEM>>>(ln, wtf, nullptr, hb,
                                                                  BT_, 4 * C_, C_);
    // 7) out = x1 + h @ W_mlp_proj
    tc_gemm<1><<<dim3(C_ / 128, BT_ / 128), 256, GEMM_SMEM>>>(hb, wtm, x1, out,
                                                              BT_, C_, 4 * C_);
}

// round 5
// speedup vs baseline: 3.8769x; 1.6821x over previous
#include <cuda_runtime.h>
#include <math.h>
#include <stdint.h>

// Problem constants
#define B_ 2
#define T_ 2048
#define C_ 768
#define H_ 12
#define HD_ 64
#define BT_ (B_ * T_)   // 4096

// ---------------------------------------------------------------------------
// Scratch (device globals; no allocation allowed)
// ---------------------------------------------------------------------------
__device__ float g_ln[BT_ * C_];          // LN output (tf32-rounded)
__device__ float g_qkv[BT_ * 3 * C_];     // QKV (tf32-rounded)
__device__ float g_vt[B_ * H_ * HD_ * T_]; // V transposed [b][h][d][t]
__device__ float g_y[BT_ * C_];           // attention output (tf32-rounded)
__device__ float g_x1[BT_ * C_];          // x + attn (fp32)
__device__ float g_h[BT_ * 4 * C_];       // gelu(fc) (tf32-rounded)
// Transposed weights [N,K] row-major (tf32-rounded)
__device__ float g_wt_qkv[3 * C_ * C_];
__device__ float g_wt_attn[C_ * C_];
__device__ float g_wt_fc[4 * C_ * C_];
__device__ float g_wt_mlp[C_ * 4 * C_];

// ---------------------------------------------------------------------------
// Helpers
// ---------------------------------------------------------------------------
__device__ __forceinline__ float to_tf32(float x) {
    uint32_t u;
    asm("cvt.rna.tf32.f32 %0, %1;" : "=r"(u) : "f"(x));
    return __uint_as_float(u);
}

__device__ __forceinline__ uint32_t smem_u32(const void* p) {
    uint32_t a;
    asm("{ .reg .u64 t; cvta.to.shared.u64 t, %1; cvt.u32.u64 %0, t; }"
        : "=r"(a) : "l"(p));
    return a;
}

#define CP_ASYNC16(dst, src) \
    asm volatile("cp.async.cg.shared.global [%0], [%1], 16;" :: "r"(dst), "l"(src))
#define CP_COMMIT() asm volatile("cp.async.commit_group;" ::: "memory")
#define CP_WAIT(n)  asm volatile("cp.async.wait_group %0;" :: "n"(n) : "memory")

__device__ __forceinline__ void mma_tf32(float* d, const float* a, const float* b) {
    asm volatile(
        "mma.sync.aligned.m16n8k8.row.col.f32.tf32.tf32.f32 "
        "{%0,%1,%2,%3}, {%4,%5,%6,%7}, {%8,%9}, {%0,%1,%2,%3};"
        : "+f"(d[0]), "+f"(d[1]), "+f"(d[2]), "+f"(d[3])
        : "r"(__float_as_uint(a[0])), "r"(__float_as_uint(a[1])),
          "r"(__float_as_uint(a[2])), "r"(__float_as_uint(a[3])),
          "r"(__float_as_uint(b[0])), "r"(__float_as_uint(b[1])));
}

// swizzled smem indices: conflict-free fragment LDS
#define SWIDX(m, k) ((m) * 32 + ((k) ^ (((m) & 7) << 2)))   // 32-float rows
#define SW64(m, k)  ((m) * 64 + ((k) ^ (((m) & 7) << 2)))   // 64-float rows

// ---------------------------------------------------------------------------
// Weight transpose: out[N,K] = tf32(in[K,N]).  grid(N/32, K/32), block(32,8)
// ---------------------------------------------------------------------------
__global__ void transpose_kernel(const float* __restrict__ in, float* __restrict__ out,
                                 int K, int N) {
    __shared__ float tile[32][33];
    int n0 = blockIdx.x * 32, k0 = blockIdx.y * 32;
    int n = n0 + threadIdx.x;
#pragma unroll
    for (int i = threadIdx.y; i < 32; i += 8)
        tile[i][threadIdx.x] = in[(size_t)(k0 + i) * N + n];
    __syncthreads();
    int k = k0 + threadIdx.x;
#pragma unroll
    for (int i = threadIdx.y; i < 32; i += 8)
        out[(size_t)(n0 + i) * K + k] = to_tf32(tile[threadIdx.x][i]);
}

// ---------------------------------------------------------------------------
// V transpose: g_vt[b][h][d][t] = qkv_v[b][t][h][d].
// grid(T/32, B*H*2), block(32,8)
// ---------------------------------------------------------------------------
__global__ void vt_kernel(const float* __restrict__ qkv, float* __restrict__ vt) {
    __shared__ float tile[32][33];
    int t0 = blockIdx.x * 32;
    int by = blockIdx.y;
    int bh = by >> 1, dt = by & 1;
    int d0 = dt * 32;
    int b = bh / H_, h = bh % H_;
    const float* src = qkv + (size_t)b * T_ * 3 * C_ + 2 * C_ + h * HD_;
#pragma unroll
    for (int i = threadIdx.y; i < 32; i += 8)
        tile[i][threadIdx.x] = src[(size_t)(t0 + i) * 3 * C_ + d0 + threadIdx.x];
    __syncthreads();
    float* dst = vt + (size_t)bh * HD_ * T_;
#pragma unroll
    for (int i = threadIdx.y; i < 32; i += 8)
        dst[(size_t)(d0 + i) * T_ + t0 + threadIdx.x] = tile[threadIdx.x][i];
}

// ---------------------------------------------------------------------------
// LayerNorm: one block (256 thr) per row of 768.  Output tf32-rounded.
// ---------------------------------------------------------------------------
__global__ void ln_kernel(const float* __restrict__ x, const float* __restrict__ g,
                          const float* __restrict__ b, float* __restrict__ out) {
    int row = blockIdx.x;
    const float* xr = x + (size_t)row * C_;
    float v[3];
    float s = 0.f, sq = 0.f;
#pragma unroll
    for (int i = 0; i < 3; i++) {
        v[i] = xr[threadIdx.x + i * 256];
        s += v[i];
        sq += v[i] * v[i];
    }
#pragma unroll
    for (int off = 16; off; off >>= 1) {
        s  += __shfl_xor_sync(0xffffffffu, s, off);
        sq += __shfl_xor_sync(0xffffffffu, sq, off);
    }
    __shared__ float ss[8], ssq[8];
    int w = threadIdx.x >> 5, lane = threadIdx.x & 31;
    if (lane == 0) { ss[w] = s; ssq[w] = sq; }
    __syncthreads();
    if (w == 0) {
        s = ss[lane & 7];
        sq = ssq[lane & 7];
#pragma unroll
        for (int off = 4; off; off >>= 1) {
            s  += __shfl_xor_sync(0xffffffffu, s, off);
            sq += __shfl_xor_sync(0xffffffffu, sq, off);
        }
        if (lane == 0) { ss[0] = s; ssq[0] = sq; }
    }
    __syncthreads();
    float mean = ss[0] * (1.0f / C_);
    float var  = ssq[0] * (1.0f / C_) - mean * mean;
    float rstd = rsqrtf(var + 1e-5f);
    float* outr = out + (size_t)row * C_;
#pragma unroll
    for (int i = 0; i < 3; i++) {
        int c = threadIdx.x + i * 256;
        outr[c] = to_tf32((v[i] - mean) * rstd * g[c] + b[c]);
    }
}

// ---------------------------------------------------------------------------
// mma.sync tf32 GEMM: C[M,N] = A[M,K] @ Bt[N,K]^T.
// BM=BN=128, BK=32, double-buffered cp.async, 256 threads, occupancy 2.
// EPI: 0 none, 1 += res, 2 GELU+tf32, 3 tf32 round
// ---------------------------------------------------------------------------
#define STAGE_FLOATS 4096   // 128*32
#define GEMM_SMEM (2 * 2 * STAGE_FLOATS * 4)   // 64KB

__device__ __forceinline__ void load_stage(uint32_t sa, uint32_t sb,
                                           const float* __restrict__ Ab,
                                           const float* __restrict__ Bb,
                                           int K, int kb, int tid) {
    int k0 = kb * 32;
#pragma unroll
    for (int t = 0; t < 4; t++) {
        int linear = tid + t * 256;
        int m = linear >> 3, ch = linear & 7;
        uint32_t sw = (uint32_t)((m * 32 + ((ch * 4) ^ ((m & 7) << 2))) * 4);
        CP_ASYNC16(sa + sw, Ab + (size_t)m * K + k0 + ch * 4);
        CP_ASYNC16(sb + sw, Bb + (size_t)m * K + k0 + ch * 4);
    }
}

template <int EPI>
__global__ __launch_bounds__(256, 2)
void tc_gemm(const float* __restrict__ A, const float* __restrict__ Bt,
             const float* __restrict__ res, float* __restrict__ Cm,
             int M, int N, int K) {
    extern __shared__ __align__(16) float dsm[];
    float* smA = dsm;
    float* smB = dsm + 2 * STAGE_FLOATS;
    uint32_t saA = smem_u32(smA);
    uint32_t saB = smem_u32(smB);

    int tid = threadIdx.x;
    int wid = tid >> 5, lane = tid & 31;
    int warp_m = wid >> 2, warp_n = wid & 3;
    int lr = lane >> 2, lc = lane & 3;
    const int KB = K >> 5;

    const float* Ab = A + (size_t)blockIdx.y * 128 * K;
    const float* Bb = Bt + (size_t)blockIdx.x * 128 * K;

    float acc[4][4][4];
#pragma unroll
    for (int i = 0; i < 4; i++)
#pragma unroll
        for (int j = 0; j < 4; j++)
#pragma unroll
            for (int r = 0; r < 4; r++) acc[i][j][r] = 0.f;

    load_stage(saA, saB, Ab, Bb, K, 0, tid);
    CP_COMMIT();

    for (int kb = 0; kb < KB; kb++) {
        int s = kb & 1;
        if (kb + 1 < KB) {
            load_stage(saA + (s ^ 1) * STAGE_FLOATS * 4,
                       saB + (s ^ 1) * STAGE_FLOATS * 4, Ab, Bb, K, kb + 1, tid);
            CP_COMMIT();
            CP_WAIT(1);
        } else {
            CP_WAIT(0);
        }
        __syncthreads();

        const float* as = smA + s * STAGE_FLOATS;
        const float* bs = smB + s * STAGE_FLOATS;
#pragma unroll
        for (int ks = 0; ks < 4; ks++) {
            int k0 = ks * 8;
            float afr[4][4], bfr[4][2];
#pragma unroll
            for (int mt = 0; mt < 4; mt++) {
                int r0 = warp_m * 64 + mt * 16 + lr;
                afr[mt][0] = as[SWIDX(r0,     k0 + lc)];
                afr[mt][1] = as[SWIDX(r0 + 8, k0 + lc)];
                afr[mt][2] = as[SWIDX(r0,     k0 + lc + 4)];
                afr[mt][3] = as[SWIDX(r0 + 8, k0 + lc + 4)];
            }
#pragma unroll
            for (int nt = 0; nt < 4; nt++) {
                int n0 = warp_n * 32 + nt * 8 + lr;
                bfr[nt][0] = bs[SWIDX(n0, k0 + lc)];
                bfr[nt][1] = bs[SWIDX(n0, k0 + lc + 4)];
            }
#pragma unroll
            for (int mt = 0; mt < 4; mt++)
#pragma unroll
                for (int nt = 0; nt < 4; nt++)
                    mma_tf32(acc[mt][nt], afr[mt], bfr[nt]);
        }
        __syncthreads();
    }

    int gm0 = blockIdx.y * 128 + warp_m * 64;
    int gn0 = blockIdx.x * 128 + warp_n * 32;
#pragma unroll
    for (int mt = 0; mt < 4; mt++) {
#pragma unroll
        for (int nt = 0; nt < 4; nt++) {
            int gm = gm0 + mt * 16 + lr;
            int gn = gn0 + nt * 8 + lc * 2;
#pragma unroll
            for (int half = 0; half < 2; half++) {
                int row = gm + half * 8;
                size_t off = (size_t)row * N + gn;
                float2 v;
                v.x = acc[mt][nt][half * 2 + 0];
                v.y = acc[mt][nt][half * 2 + 1];
                if (EPI == 1) {
                    float2 rs = *(const float2*)(res + off);
                    v.x += rs.x; v.y += rs.y;
                }
                if (EPI == 2) {
                    v.x = to_tf32(0.5f * v.x * (1.0f + erff(v.x * 0.7071067811865475f)));
                    v.y = to_tf32(0.5f * v.y * (1.0f + erff(v.y * 0.7071067811865475f)));
                }
                if (EPI == 3) {
                    v.x = to_tf32(v.x);
                    v.y = to_tf32(v.y);
                }
                *(float2*)(Cm + off) = v;
            }
        }
    }
}

// ---------------------------------------------------------------------------
// Tensor-core flash attention (tf32, causal). Grid: (T/64, B*H). 128 threads.
// 4 warps x 16 query rows; key tiles of 64; double-buffered K/Vt via cp.async.
// smem floats: Qs/Ps [0,4096) | Ks[2] [4096,12288) | Vt[2] [12288,20480)
// ---------------------------------------------------------------------------
#define ATTN_SMEM (20480 * 4)

__device__ __forceinline__ void attn_load_kv(uint32_t sb, const float* __restrict__ kbase,
                                             const float* __restrict__ vtb,
                                             int j, int s, int tid) {
    uint32_t kdst = sb + (uint32_t)(4096 + s * 4096) * 4;
    uint32_t vdst = sb + (uint32_t)(12288 + s * 4096) * 4;
#pragma unroll
    for (int t = 0; t < 8; t++) {
        int linear = tid + t * 128;
        int r = linear >> 4, ch = linear & 15;
        uint32_t sw = (uint32_t)((r * 64 + ((ch * 4) ^ ((r & 7) << 2))) * 4);
        CP_ASYNC16(kdst + sw, kbase + (size_t)(j * 64 + r) * 3 * C_ + ch * 4);
        CP_ASYNC16(vdst + sw, vtb + (size_t)r * T_ + j * 64 + ch * 4);
    }
}

__global__ __launch_bounds__(128)
void attn_tc(const float* __restrict__ qkv, const float* __restrict__ vt,
             float* __restrict__ y) {
    extern __shared__ __align__(16) float smf[];
    uint32_t sb = smem_u32(smf);

    int qb = blockIdx.x, bh = blockIdx.y;
    int b = bh / H_, h = bh % H_;
    int tid = threadIdx.x, wid = tid >> 5, lane = tid & 31;
    int lr = lane >> 2, lc = lane & 3;

    const float* qbase = qkv + (size_t)b * T_ * 3 * C_ + h * HD_;
    const float* kbase = qbase + C_;
    const float* vtb = vt + (size_t)bh * HD_ * T_;

    // load Q tile (group 0)
#pragma unroll
    for (int t = 0; t < 8; t++) {
        int linear = tid + t * 128;
        int r = linear >> 4, ch = linear & 15;
        uint32_t sw = (uint32_t)((r * 64 + ((ch * 4) ^ ((r & 7) << 2))) * 4);
        CP_ASYNC16(sb + sw, qbase + (size_t)(qb * 64 + r) * 3 * C_ + ch * 4);
    }
    CP_COMMIT();
    // load K/Vt tile 0 (group 1)
    attn_load_kv(sb, kbase, vtb, 0, 0, tid);
    CP_COMMIT();

    CP_WAIT(1);          // Q ready
    __syncthreads();

    // Q fragments to registers (per-warp rows [16*wid, 16*wid+16))
    int r0 = wid * 16 + lr;
    float qfr[8][4];
#pragma unroll
    for (int ks = 0; ks < 8; ks++) {
        qfr[ks][0] = smf[SW64(r0,     ks * 8 + lc)];
        qfr[ks][1] = smf[SW64(r0 + 8, ks * 8 + lc)];
        qfr[ks][2] = smf[SW64(r0,     ks * 8 + lc + 4)];
        qfr[ks][3] = smf[SW64(r0 + 8, ks * 8 + lc + 4)];
    }

    float oacc[8][4];
#pragma unroll
    for (int i = 0; i < 8; i++)
#pragma unroll
        for (int e = 0; e < 4; e++) oacc[i][e] = 0.f;
    float m0 = -1e30f, m1 = -1e30f, l0 = 0.f, l1 = 0.f;

    int rg0 = qb * 64 + r0;

    for (int j = 0; j <= qb; j++) {
        int s = j & 1;
        if (j < qb) {
            attn_load_kv(sb, kbase, vtb, j + 1, s ^ 1, tid);
            CP_COMMIT();
            CP_WAIT(1);
        } else {
            CP_WAIT(0);
        }
        __syncthreads();

        const float* ksm = smf + 4096 + s * 4096;
        const float* vsm = smf + 12288 + s * 4096;

        // S = Q @ K^T
        float sacc[8][4];
#pragma unroll
        for (int nf = 0; nf < 8; nf++)
#pragma unroll
            for (int e = 0; e < 4; e++) sacc[nf][e] = 0.f;
#pragma unroll
        for (int nf = 0; nf < 8; nf++) {
            int n0 = nf * 8 + lr;
#pragma unroll
            for (int ks = 0; ks < 8; ks++) {
                float bfr[2];
                bfr[0] = ksm[SW64(n0, ks * 8 + lc)];
                bfr[1] = ksm[SW64(n0, ks * 8 + lc + 4)];
                mma_tf32(sacc[nf], qfr[ks], bfr);
            }
        }

        // scale + causal mask (diagonal tile only)
#pragma unroll
        for (int nf = 0; nf < 8; nf++) {
#pragma unroll
            for (int e = 0; e < 4; e++) {
                float v = sacc[nf][e] * 0.125f;
                if (j == qb) {
                    int col = j * 64 + nf * 8 + 2 * lc + (e & 1);
                    int row = (e < 2) ? rg0 : rg0 + 8;
                    if (col > row) v = -1e30f;
                }
                sacc[nf][e] = v;
            }
        }

        // online softmax (rows lr and lr+8; quad = 4 lanes share a row)
        float ml0 = -1e30f, ml1 = -1e30f;
#pragma unroll
        for (int nf = 0; nf < 8; nf++) {
            ml0 = fmaxf(ml0, fmaxf(sacc[nf][0], sacc[nf][1]));
            ml1 = fmaxf(ml1, fmaxf(sacc[nf][2], sacc[nf][3]));
        }
#pragma unroll
        for (int off = 1; off < 4; off <<= 1) {
            ml0 = fmaxf(ml0, __shfl_xor_sync(0xffffffffu, ml0, off));
            ml1 = fmaxf(ml1, __shfl_xor_sync(0xffffffffu, ml1, off));
        }
        float mn0 = fmaxf(m0, ml0), mn1 = fmaxf(m1, ml1);
        float c0 = __expf(m0 - mn0), c1 = __expf(m1 - mn1);
        float ls0 = 0.f, ls1 = 0.f;
#pragma unroll
        for (int nf = 0; nf < 8; nf++) {
            int colb = nf * 8 + 2 * lc;
            float p0 = __expf(sacc[nf][0] - mn0);
            float p1 = __expf(sacc[nf][1] - mn0);
            float p2 = __expf(sacc[nf][2] - mn1);
            float p3 = __expf(sacc[nf][3] - mn1);
            ls0 += p0 + p1;
            ls1 += p2 + p3;
            smf[SW64(r0,     colb)]     = p0;
            smf[SW64(r0,     colb + 1)] = p1;
            smf[SW64(r0 + 8, colb)]     = p2;
            smf[SW64(r0 + 8, colb + 1)] = p3;
        }
#pragma unroll
        for (int off = 1; off < 4; off <<= 1) {
            ls0 += __shfl_xor_sync(0xffffffffu, ls0, off);
            ls1 += __shfl_xor_sync(0xffffffffu, ls1, off);
        }
        l0 = l0 * c0 + ls0;
        l1 = l1 * c1 + ls1;
        m0 = mn0; m1 = mn1;
#pragma unroll
        for (int nf = 0; nf < 8; nf++) {
            oacc[nf][0] *= c0;
            oacc[nf][1] *= c0;
            oacc[nf][2] *= c1;
            oacc[nf][3] *= c1;
        }
        __syncwarp();

        // O += P @ V  (A = P from per-warp smem region, B = Vt)
#pragma unroll
        for (int ks = 0; ks < 8; ks++) {
            float pafr[4];
            pafr[0] = to_tf32(smf[SW64(r0,     ks * 8 + lc)]);
            pafr[1] = to_tf32(smf[SW64(r0 + 8, ks * 8 + lc)]);
            pafr[2] = to_tf32(smf[SW64(r0,     ks * 8 + lc + 4)]);
            pafr[3] = to_tf32(smf[SW64(r0 + 8, ks * 8 + lc + 4)]);
#pragma unroll
            for (int nf = 0; nf < 8; nf++) {
                float bfr[2];
                bfr[0] = vsm[SW64(nf * 8 + lr, ks * 8 + lc)];
                bfr[1] = vsm[SW64(nf * 8 + lr, ks * 8 + lc + 4)];
                mma_tf32(oacc[nf], pafr, bfr);
            }
        }
        __syncthreads();
    }

    // write y (tf32-rounded, ready for proj GEMM)
    float inv0 = 1.0f / l0, inv1 = 1.0f / l1;
#pragma unroll
    for (int nf = 0; nf < 8; nf++) {
        int gc = h * HD_ + nf * 8 + 2 * lc;
        size_t o0 = (size_t)(b * T_ + rg0) * C_ + gc;
        size_t o1 = (size_t)(b * T_ + rg0 + 8) * C_ + gc;
        float2 v0, v1;
        v0.x = to_tf32(oacc[nf][0] * inv0);
        v0.y = to_tf32(oacc[nf][1] * inv0);
        v1.x = to_tf32(oacc[nf][2] * inv1);
        v1.y = to_tf32(oacc[nf][3] * inv1);
        *(float2*)(y + o0) = v0;
        *(float2*)(y + o1) = v1;
    }
}

// ---------------------------------------------------------------------------
// Launch
// ---------------------------------------------------------------------------
extern "C" void kernel_launch(void* const* d_in, const int* in_sizes, int n_in,
                              void* d_out, int out_size) {
    const float* x       = (const float*)d_in[0];
    const float* ln1_g   = (const float*)d_in[1];
    const float* ln1_b   = (const float*)d_in[2];
    const float* W_qkv   = (const float*)d_in[3];
    const float* W_attn  = (const float*)d_in[4];
    const float* ln2_g   = (const float*)d_in[5];
    const float* ln2_b   = (const float*)d_in[6];
    const float* W_fc    = (const float*)d_in[7];
    const float* W_mlp   = (const float*)d_in[8];
    float* out = (float*)d_out;

    float *ln, *qkv, *vtb, *yb, *x1, *hb;
    float *wtq, *wta, *wtf, *wtm;
    cudaGetSymbolAddress((void**)&ln, g_ln);
    cudaGetSymbolAddress((void**)&qkv, g_qkv);
    cudaGetSymbolAddress((void**)&vtb, g_vt);
    cudaGetSymbolAddress((void**)&yb, g_y);
    cudaGetSymbolAddress((void**)&x1, g_x1);
    cudaGetSymbolAddress((void**)&hb, g_h);
    cudaGetSymbolAddress((void**)&wtq, g_wt_qkv);
    cudaGetSymbolAddress((void**)&wta, g_wt_attn);
    cudaGetSymbolAddress((void**)&wtf, g_wt_fc);
    cudaGetSymbolAddress((void**)&wtm, g_wt_mlp);

    cudaFuncSetAttribute(tc_gemm<1>, cudaFuncAttributeMaxDynamicSharedMemorySize, GEMM_SMEM);
    cudaFuncSetAttribute(tc_gemm<2>, cudaFuncAttributeMaxDynamicSharedMemorySize, GEMM_SMEM);
    cudaFuncSetAttribute(tc_gemm<3>, cudaFuncAttributeMaxDynamicSharedMemorySize, GEMM_SMEM);
    cudaFuncSetAttribute(attn_tc, cudaFuncAttributeMaxDynamicSharedMemorySize, ATTN_SMEM);

    // 0) transpose weights to [N,K] (tf32-rounded)
    transpose_kernel<<<dim3(3 * C_ / 32, C_ / 32), dim3(32, 8)>>>(W_qkv, wtq, C_, 3 * C_);
    transpose_kernel<<<dim3(C_ / 32, C_ / 32), dim3(32, 8)>>>(W_attn, wta, C_, C_);
    transpose_kernel<<<dim3(4 * C_ / 32, C_ / 32), dim3(32, 8)>>>(W_fc, wtf, C_, 4 * C_);
    transpose_kernel<<<dim3(C_ / 32, 4 * C_ / 32), dim3(32, 8)>>>(W_mlp, wtm, 4 * C_, C_);

    // 1) LN1
    ln_kernel<<<BT_, 256>>>(x, ln1_g, ln1_b, ln);
    // 2) QKV = ln1 @ W_qkv (tf32-rounded output)
    tc_gemm<3><<<dim3(3 * C_ / 128, BT_ / 128), 256, GEMM_SMEM>>>(ln, wtq, nullptr, qkv,
                                                                  BT_, 3 * C_, C_);
    // 3) V transpose
    vt_kernel<<<dim3(T_ / 32, B_ * H_ * 2), dim3(32, 8)>>>(qkv, vtb);
    // 4) tensor-core causal flash attention
    attn_tc<<<dim3(T_ / 64, B_ * H_), 128, ATTN_SMEM>>>(qkv, vtb, yb);
    // 5) x1 = x + y @ W_attn_proj
    tc_gemm<1><<<dim3(C_ / 128, BT_ / 128), 256, GEMM_SMEM>>>(yb, wta, x, x1,
                                                              BT_, C_, C_);
    // 6) LN2
    ln_kernel<<<BT_, 256>>>(x1, ln2_g, ln2_b, ln);
    // 7) h = gelu(ln2 @ W_fc)
    tc_gemm<2><<<dim3(4 * C_ / 128, BT_ / 128), 256, GEMM_SMEM>>>(ln, wtf, nullptr, hb,
                                                                  BT_, 4 * C_, C_);
    // 8) out = x1 + h @ W_mlp_proj
    tc_gemm<1><<<dim3(C_ / 128, BT_ / 128), 256, GEMM_SMEM>>>(hb, wtm, x1, out,
                                                              BT_, C_, 4 * C_);
}